// round 15
// baseline (speedup 1.0000x reference)
#include <cuda_runtime.h>
#include <cstdint>

#define ROWS 84
#define SLEN 131072
#define BPR 16                    // blocks per row -> 1344 worker blocks
#define THREADS 256
#define CHUNK (SLEN / BPR)        // 8192 elements per array per block
#define ITERS (CHUNK / (THREADS * 4))  // 8 float4 iterations per thread
#define PF_AHEAD 4                // prefetch distance in iterations (16KB/array)
#define ITER_BYTES (THREADS * 16) // 4096 B per array per iteration
#define GRID (ROWS * BPR)         // workers; +1 finalizer block

// scratch: per (row, chunk) partial sums for ST0-side and ST1-side
__device__ float g_partial[ROWS * BPR * 2];
__device__ unsigned int g_count = 0;

__device__ __forceinline__ float sigf(float x) {
    return __fdividef(1.0f, 1.0f + __expf(-x));
}

__device__ __forceinline__ void l2_prefetch(const void* p) {
    asm volatile("cp.async.bulk.prefetch.L2.global [%0], %1;"
                 :: "l"(p), "r"((uint32_t)ITER_BYTES) : "memory");
}

// thread t (< 84): entry t of the 84-long nested-product vector, reference order
__device__ __forceinline__ float prob_entry(const float* p, int t) {
    int i = t / 21;
    int r = t - i * 21;
    if (r == 0) return p[i];
    r -= 1;
    int j = r / 5;
    int s = r - j * 5;
    float pij = p[i] * p[j];
    if (s == 0) return pij;
    return pij * p[s - 1];
}

__device__ __forceinline__ void softmax4(const float* __restrict__ l, float* p) {
    float mx = fmaxf(fmaxf(l[0], l[1]), fmaxf(l[2], l[3]));
    float e0 = __expf(l[0] - mx), e1 = __expf(l[1] - mx),
          e2 = __expf(l[2] - mx), e3 = __expf(l[3] - mx);
    float inv = __fdividef(1.0f, e0 + e1 + e2 + e3);
    p[0] = e0 * inv; p[1] = e1 * inv; p[2] = e2 * inv; p[3] = e3 * inv;
}

__global__ __launch_bounds__(THREADS)
void fused_kernel(const float* __restrict__ ST0, const float* __restrict__ W0,
                  const float* __restrict__ ST1, const float* __restrict__ W1,
                  const float* __restrict__ BEV, const float* __restrict__ BEV_p,
                  const float* __restrict__ B,
                  const float* __restrict__ probs0, const float* __restrict__ probs1,
                  const float* __restrict__ probs2, const float* __restrict__ probs3,
                  const float* __restrict__ probs4,
                  float* __restrict__ out) {
    __shared__ float sh0[THREADS / 32], sh1[THREADS / 32];
    const int bid = blockIdx.x;
    const int tid = threadIdx.x;
    const int warp = tid >> 5, lane = tid & 31;

    if (bid == GRID) {
        // ---- dedicated finalizer block (only acquire site) ----
        if (tid == 0) {
            unsigned int v;
            do {
                asm volatile("ld.acquire.gpu.global.u32 %0, [%1];"
                             : "=r"(v) : "l"(&g_count) : "memory");
                if (v < GRID) __nanosleep(128);
            } while (v < GRID);
        }
        __syncthreads();
        float c = 0.0f;
        if (tid < ROWS) {
            float a0 = 0.0f, a1 = 0.0f;
            #pragma unroll
            for (int k = 0; k < BPR; ++k) {
                const int slot = (tid * BPR + k) * 2;
                a0 += g_partial[slot];
                a1 += g_partial[slot + 1];
            }
            float p[4];
            softmax4(probs0, p);
            c = prob_entry(p, tid) * a0;
            float esum = 0.0f;
            softmax4(probs1, p); esum += prob_entry(p, tid);
            softmax4(probs2, p); esum += prob_entry(p, tid);
            softmax4(probs3, p); esum += prob_entry(p, tid);
            softmax4(probs4, p); esum += prob_entry(p, tid);
            c += esum * a1;
        }
        #pragma unroll
        for (int o = 16; o > 0; o >>= 1)
            c += __shfl_down_sync(0xFFFFFFFFu, c, o);
        if (lane == 0) sh0[warp] = c;
        __syncthreads();
        if (tid == 0) {
            float acc = 0.0f;
            #pragma unroll
            for (int w = 0; w < THREADS / 32; ++w) acc += sh0[w];
            out[0] = acc * 0.2f;
            g_count = 0;   // reset for next graph replay
        }
        return;
    }

    // ---- worker block: LDG mainloop + bulk L2 prefetch ahead ----
    const int row = bid >> 4;           // bid / BPR
    const int chunk = bid & (BPR - 1);  // bid % BPR
    const float b = B[0];
    const float bb = b * (fmaxf(BEV_p[0], 0.0f) * BEV[0]);  // sig(b*st + bb)

    const size_t base = (size_t)row * SLEN + (size_t)chunk * CHUNK;
    const float* p0a = ST0 + base;
    const float* p1a = W0  + base;
    const float* p2a = ST1 + base;
    const float* p3a = W1  + base;

    // prologue: warm L2 for the first PF_AHEAD iterations
    if (tid == 0) {
        #pragma unroll
        for (int k = 0; k < PF_AHEAD; ++k) {
            const size_t off = (size_t)k * (THREADS * 4);
            l2_prefetch(p0a + off);
            l2_prefetch(p1a + off);
            l2_prefetch(p2a + off);
            l2_prefetch(p3a + off);
        }
    }

    const float4* st0 = (const float4*)p0a;
    const float4* w0  = (const float4*)p1a;
    const float4* st1 = (const float4*)p2a;
    const float4* w1  = (const float4*)p3a;

    float s0 = 0.0f, s1 = 0.0f;
    #pragma unroll
    for (int it = 0; it < ITERS; ++it) {
        // keep the prefetch window PF_AHEAD iterations ahead of the LDG stream
        if (tid == 0 && it + PF_AHEAD < ITERS) {
            const size_t off = (size_t)(it + PF_AHEAD) * (THREADS * 4);
            l2_prefetch(p0a + off);
            l2_prefetch(p1a + off);
            l2_prefetch(p2a + off);
            l2_prefetch(p3a + off);
        }
        const int idx = it * THREADS + tid;
        float4 a0 = st0[idx];
        float4 c0 = w0[idx];
        float4 a1 = st1[idx];
        float4 c1 = w1[idx];
        s0 += sigf(fmaf(b, a0.x, bb)) * c0.x;
        s0 += sigf(fmaf(b, a0.y, bb)) * c0.y;
        s0 += sigf(fmaf(b, a0.z, bb)) * c0.z;
        s0 += sigf(fmaf(b, a0.w, bb)) * c0.w;
        s1 += sigf(fmaf(b, a1.x, bb)) * c1.x;
        s1 += sigf(fmaf(b, a1.y, bb)) * c1.y;
        s1 += sigf(fmaf(b, a1.z, bb)) * c1.z;
        s1 += sigf(fmaf(b, a1.w, bb)) * c1.w;
    }

    // block reduction of the two partial dot products
    #pragma unroll
    for (int o = 16; o > 0; o >>= 1) {
        s0 += __shfl_down_sync(0xFFFFFFFFu, s0, o);
        s1 += __shfl_down_sync(0xFFFFFFFFu, s1, o);
    }
    if (lane == 0) { sh0[warp] = s0; sh1[warp] = s1; }
    __syncthreads();
    if (tid == 0) {
        float t0 = 0.0f, t1 = 0.0f;
        #pragma unroll
        for (int w = 0; w < THREADS / 32; ++w) { t0 += sh0[w]; t1 += sh1[w]; }
        const int slot = (row * BPR + chunk) * 2;
        g_partial[slot]     = t0;
        g_partial[slot + 1] = t1;
        // release-only increment: orders the stores above, no L1 invalidate
        asm volatile("red.release.gpu.global.add.u32 [%0], %1;"
                     :: "l"(&g_count), "r"(1u) : "memory");
    }
}

extern "C" void kernel_launch(void* const* d_in, const int* in_sizes, int n_in,
                              void* d_out, int out_size) {
    const float* BEV   = (const float*)d_in[0];
    const float* ST0   = (const float*)d_in[1];
    const float* W0    = (const float*)d_in[2];
    const float* ST1   = (const float*)d_in[3];
    const float* W1    = (const float*)d_in[4];
    const float* p0    = (const float*)d_in[5];
    const float* p1    = (const float*)d_in[6];
    const float* p2    = (const float*)d_in[7];
    const float* p3    = (const float*)d_in[8];
    const float* p4    = (const float*)d_in[9];
    const float* BEV_p = (const float*)d_in[10];
    const float* B     = (const float*)d_in[11];
    float* out = (float*)d_out;

    fused_kernel<<<GRID + 1, THREADS>>>(ST0, W0, ST1, W1, BEV, BEV_p, B,
                                        p0, p1, p2, p3, p4, out);
}